// round 15
// baseline (speedup 1.0000x reference)
#include <cuda_runtime.h>
#include <cuda_fp16.h>
#include <math.h>
#include <stdint.h>

#define Bb 256
#define Nn 512
#define Dd 64
#define TOK (Bb * Nn)        // 131072 tokens
#define TILES (TOK / 64)     // 2048 token tiles
#define SPITCH 72            // smem pitch (fp16): 144B, ldmatrix conflict-free
#define ROWB (SPITCH * 2)    // 144 bytes per smem row
#define TILEB (64 * ROWB)    // 9216 bytes per 64x64 fp16 tile
#define FPAD 68              // fp32 smem pitch

// ---------------------------------------------------------------------------
// Global scratch (allocation-free rule: __device__ globals).
// ---------------------------------------------------------------------------
__device__ __half g_xhi[TOK * Dd];        // x split (fp16 hi/lo)
__device__ __half g_xlo[TOK * Dd];        // lo used only by the Q' prologue
__device__ float  g_gate[2][TOK * Dd];    // gate partial = (P.x).M_vd [br]
__device__ __half g_whi[4][4096];         // M_qk[2] (log2e-scaled), M_vd[2] hi
__device__ __half g_wlo[4][4096];         // split lo

// ---------------------------------------------------------------------------
// Helpers
// ---------------------------------------------------------------------------
__device__ __forceinline__ uint32_t smem_u32(const void* p) {
    uint32_t a;
    asm("{ .reg .u64 t; cvta.to.shared.u64 t, %1; cvt.u32.u64 %0, t; }" : "=r"(a) : "l"(p));
    return a;
}
__device__ __forceinline__ float ex2f(float x) {
    float r;
    asm("ex2.approx.f32 %0, %1;" : "=f"(r) : "f"(x));
    return r;
}
__device__ __forceinline__ uint32_t pack_h2(float a, float b) {
    __half2 t = __floats2half2_rn(a, b);
    return *(uint32_t*)&t;
}
__device__ __forceinline__ void split_h(float x, float& hi, float& lo) {
    hi = __half2float(__float2half_rn(x));
    lo = x - hi;
}
__device__ __forceinline__ void split_pack2(float a, float b, uint32_t& h, uint32_t& l) {
    float ha, la, hb, lb;
    split_h(a, ha, la);
    split_h(b, hb, lb);
    h = pack_h2(ha, hb);
    l = pack_h2(la, lb);
}

#define LDSM_X4(r0, r1, r2, r3, addr) \
    asm volatile("ldmatrix.sync.aligned.m8n8.x4.shared.b16 {%0,%1,%2,%3}, [%4];" \
                 : "=r"(r0), "=r"(r1), "=r"(r2), "=r"(r3) : "r"(addr))
#define LDSM_X4_T(r0, r1, r2, r3, addr) \
    asm volatile("ldmatrix.sync.aligned.m8n8.x4.trans.shared.b16 {%0,%1,%2,%3}, [%4];" \
                 : "=r"(r0), "=r"(r1), "=r"(r2), "=r"(r3) : "r"(addr))

#define CP_ASYNC16(dst, src) \
    asm volatile("cp.async.cg.shared.global [%0], [%1], 16;" :: "r"(dst), "l"(src))
#define CP_COMMIT() asm volatile("cp.async.commit_group;")
#define CP_WAIT(n)  asm volatile("cp.async.wait_group %0;" :: "n"(n))

__device__ __forceinline__ void mma16816(float c[4], const uint32_t a[4],
                                         uint32_t b0, uint32_t b1) {
    asm volatile(
        "mma.sync.aligned.m16n8k16.row.col.f32.f16.f16.f32 "
        "{%0,%1,%2,%3}, {%4,%5,%6,%7}, {%8,%9}, {%0,%1,%2,%3};"
        : "+f"(c[0]), "+f"(c[1]), "+f"(c[2]), "+f"(c[3])
        : "r"(a[0]), "r"(a[1]), "r"(a[2]), "r"(a[3]), "r"(b0), "r"(b1));
}

// cp.async a 64x64 fp16 tile (row-major, 128B rows) into pitch-144B smem.
__device__ __forceinline__ void cp_tile(uint32_t smem_dst, const __half* src,
                                        int tid, int nthreads) {
    for (int i = tid; i < 512; i += nthreads) {
        uint32_t d = smem_dst + (uint32_t)((i >> 3) * ROWB + (i & 7) * 16);
        CP_ASYNC16(d, src + i * 8);
    }
}

// ---------------------------------------------------------------------------
// Kernel 0: precompute fused weight products (fp32), split to fp16 hi/lo.
//   idx 0,1: M_qk[br] = (0.125*log2e) * Wq * Wk^T   (scores in log2-domain)
//   idx 2,3: M_vd[br] = Wv * Wd
// ---------------------------------------------------------------------------
__global__ __launch_bounds__(256) void mm_w_kernel(
    const float* __restrict__ Wqt, const float* __restrict__ Wkt,
    const float* __restrict__ Wqs, const float* __restrict__ Wks,
    const float* __restrict__ Wvt, const float* __restrict__ Wdt,
    const float* __restrict__ Wvs, const float* __restrict__ Wds)
{
    __shared__ float As[64][FPAD];
    __shared__ float Bs[64][FPAD];

    const int idx = blockIdx.x;
    const int tid = threadIdx.x;
    const int ty = tid >> 4;
    const int tx = tid & 15;

    const float LOG2E = 1.4426950408889634f;
    const float* A;
    const float* B;
    bool transB;
    float sc;
    switch (idx) {
        case 0:  A = Wqt; B = Wkt; transB = true;  sc = 0.125f * LOG2E; break;
        case 1:  A = Wqs; B = Wks; transB = true;  sc = 0.125f * LOG2E; break;
        case 2:  A = Wvt; B = Wdt; transB = false; sc = 1.0f;           break;
        default: A = Wvs; B = Wds; transB = false; sc = 1.0f;           break;
    }

    for (int i = tid; i < 1024; i += 256) {
        int r = i >> 4;
        int c = (i & 15) << 2;
        *(float4*)&As[r][c] = *(const float4*)(A + r * 64 + c);
        float4 bv = *(const float4*)(B + r * 64 + c);
        if (transB) {
            Bs[c + 0][r] = bv.x;
            Bs[c + 1][r] = bv.y;
            Bs[c + 2][r] = bv.z;
            Bs[c + 3][r] = bv.w;
        } else {
            *(float4*)&Bs[r][c] = bv;
        }
    }
    __syncthreads();

    float acc[4][4] = {};
#pragma unroll
    for (int k = 0; k < 64; k += 4) {
        float a[4][4];
#pragma unroll
        for (int i = 0; i < 4; i++)
            *(float4*)a[i] = *(const float4*)&As[4 * ty + i][k];
#pragma unroll
        for (int kk = 0; kk < 4; kk++) {
            float4 b4 = *(const float4*)&Bs[k + kk][4 * tx];
#pragma unroll
            for (int i = 0; i < 4; i++) {
                acc[i][0] += a[i][kk] * b4.x;
                acc[i][1] += a[i][kk] * b4.y;
                acc[i][2] += a[i][kk] * b4.z;
                acc[i][3] += a[i][kk] * b4.w;
            }
        }
    }

#pragma unroll
    for (int i = 0; i < 4; i++) {
        uint2 h, l;
        split_pack2(acc[i][0] * sc, acc[i][1] * sc, h.x, l.x);
        split_pack2(acc[i][2] * sc, acc[i][3] * sc, h.y, l.y);
        int off = (4 * ty + i) * 64 + 4 * tx;
        *(uint2*)&g_whi[idx][off] = h;
        *(uint2*)&g_wlo[idx][off] = l;
    }
}

// ---------------------------------------------------------------------------
// Kernel 1: split x into fp16 hi/lo (pure streaming).
// ---------------------------------------------------------------------------
__global__ __launch_bounds__(256) void xsplit_kernel(const float* __restrict__ x)
{
    const size_t i = ((size_t)blockIdx.x * 256 + threadIdx.x) * 4;
    float4 v = *(const float4*)(x + i);
    uint2 h, l;
    split_pack2(v.x, v.y, h.x, l.x);
    split_pack2(v.z, v.w, h.y, l.y);
    *(uint2*)(g_xhi + i) = h;
    *(uint2*)(g_xlo + i) = l;
}

// ---------------------------------------------------------------------------
// Kernel 2: fused Q'-projection + flash attention + output projection.
// Precision plan:
//   Q' prologue: 3-pass (x lo read from gmem; exact hi operand for S).
//   S = Qhi.Xhi : 1-pass.
//   T = Phi.Xhi : 1-pass — T is quantized to fp16 in the epilogue anyway,
//                 so the dropped x_lo term is below existing quantization.
//   G epilogue  : 2-pass (Thi.Mhi + Thi.Mlo).
// Mainloop streams ONLY Xhi: 3-stage single-tile ring; M_qk/M_vd in fixed
// slots 3,4 (M_vd streamed in during kt=7). Unnormalized P = 2^s; deferred
// l-reduction. grid (8,256,2), 128 thr, 4 blocks/SM. MMA/warp = 672.
// Dynamic smem = 5 tiles = 46080B.
// ---------------------------------------------------------------------------
#define AT_STG(s) ((s) * TILEB)
#define AT_MH (3 * TILEB)
#define AT_ML (4 * TILEB)
#define AT_SMEM (5 * TILEB)

__global__ __launch_bounds__(128, 4) void attn_kernel()
{
    extern __shared__ char sm[];
    const uint32_t smb = smem_u32(sm);

    const int tid  = threadIdx.x;
    const int wid  = tid >> 5;
    const int lane = tid & 31;
    const int g    = lane >> 2;
    const int q4   = lane & 3;
    const int qt = blockIdx.x;
    const int b  = blockIdx.y;
    const int br = blockIdx.z;

    const __half* Xg_h = g_xhi + (size_t)b * Nn * 64;
    const __half* Xg_l = g_xlo + (size_t)b * Nn * 64;

    // Group 0: M_qk (hi/lo).  Group 1: x0.  Group 2: x1.
    cp_tile(smb + AT_MH, g_whi[br], tid, 128);
    cp_tile(smb + AT_ML, g_wlo[br], tid, 128);
    CP_COMMIT();
    cp_tile(smb + AT_STG(0), Xg_h, tid, 128);
    CP_COMMIT();
    cp_tile(smb + AT_STG(1), Xg_h + 4096, tid, 128);
    CP_COMMIT();

    // x(qt) A-fragments from gmem (overlaps the async loads).
    const __half* XQh = Xg_h + (size_t)qt * 4096;
    const __half* XQl = Xg_l + (size_t)qt * 4096;
    const int r0 = wid * 16 + g;
    uint32_t xqhi[4][4], xqlo[4][4];
#pragma unroll
    for (int ks = 0; ks < 4; ks++) {
        int base = 16 * ks + 2 * q4;
        xqhi[ks][0] = *(const uint32_t*)(XQh + (size_t)r0 * 64 + base);
        xqhi[ks][1] = *(const uint32_t*)(XQh + (size_t)(r0 + 8) * 64 + base);
        xqhi[ks][2] = *(const uint32_t*)(XQh + (size_t)r0 * 64 + base + 8);
        xqhi[ks][3] = *(const uint32_t*)(XQh + (size_t)(r0 + 8) * 64 + base + 8);
        xqlo[ks][0] = *(const uint32_t*)(XQl + (size_t)r0 * 64 + base);
        xqlo[ks][1] = *(const uint32_t*)(XQl + (size_t)(r0 + 8) * 64 + base);
        xqlo[ks][2] = *(const uint32_t*)(XQl + (size_t)r0 * 64 + base + 8);
        xqlo[ks][3] = *(const uint32_t*)(XQl + (size_t)(r0 + 8) * 64 + base + 8);
    }

    const int k_row = (lane & 7) + ((lane >> 4) << 3);
    const int k_col = ((lane >> 3) & 1) << 4;
    const int v_row = (lane & 7) + (((lane >> 3) & 1) << 3);
    const int v_col = (lane >> 4) << 4;

    // ---- Prologue GEMM: Q' = x(qt) . M_qk (3-pass; hi operand exact) ----
    CP_WAIT(2);        // M_qk resident
    __syncthreads();

    uint32_t qhi[4][4];
    {
        const uint32_t mh = smb + AT_MH;
        const uint32_t ml = smb + AT_ML;
        float qacc[8][4];
#pragma unroll
        for (int j = 0; j < 8; j++)
#pragma unroll
            for (int e = 0; e < 4; e++) qacc[j][e] = 0.f;

#pragma unroll
        for (int jj = 0; jj < 4; jj++) {
#pragma unroll
            for (int ks = 0; ks < 4; ks++) {
                uint32_t off = (uint32_t)((16 * ks + v_row) * ROWB + 32 * jj + v_col);
                uint32_t bh0, bh1, bh2, bh3, bl0, bl1, bl2, bl3;
                LDSM_X4_T(bh0, bh1, bh2, bh3, mh + off);
                LDSM_X4_T(bl0, bl1, bl2, bl3, ml + off);
                mma16816(qacc[2 * jj],     xqhi[ks], bh0, bh1);
                mma16816(qacc[2 * jj],     xqlo[ks], bh0, bh1);
                mma16816(qacc[2 * jj],     xqhi[ks], bl0, bl1);
                mma16816(qacc[2 * jj + 1], xqhi[ks], bh2, bh3);
                mma16816(qacc[2 * jj + 1], xqlo[ks], bh2, bh3);
                mma16816(qacc[2 * jj + 1], xqhi[ks], bl2, bl3);
            }
        }
        // A-fragment repack, hi only (S is 1-pass).
#pragma unroll
        for (int ks = 0; ks < 4; ks++) {
            int t0 = 2 * ks, t1 = 2 * ks + 1;
            qhi[ks][0] = pack_h2(qacc[t0][0], qacc[t0][1]);
            qhi[ks][1] = pack_h2(qacc[t0][2], qacc[t0][3]);
            qhi[ks][2] = pack_h2(qacc[t1][0], qacc[t1][1]);
            qhi[ks][3] = pack_h2(qacc[t1][2], qacc[t1][3]);
        }
    }

    float O[8][4];
#pragma unroll
    for (int j = 0; j < 8; j++)
#pragma unroll
        for (int e = 0; e < 4; e++) O[j][e] = 0.f;
    float l0 = 0.f, l1 = 0.f;   // unnormalized row sums (quad-partial)

    for (int kt = 0; kt < 8; kt++) {
        if (kt < 7) { CP_WAIT(1); } else { CP_WAIT(0); }
        __syncthreads();  // stage kt visible; all readers of the reused slot retired

        if (kt < 6) {
            cp_tile(smb + AT_STG((kt + 2) % 3), Xg_h + (size_t)(kt + 2) * 4096, tid, 128);
            CP_COMMIT();
        } else if (kt == 7) {
            // M_qk fully consumed in the prologue; stream M_vd into its slots.
            cp_tile(smb + AT_MH, g_whi[2 + br], tid, 128);
            cp_tile(smb + AT_ML, g_wlo[2 + br], tid, 128);
            CP_COMMIT();
        }

        const uint32_t xh = smb + AT_STG(kt % 3);

        // ---- S~ = Qhi.Xhi  (1-pass, log2 scores) ----
        float s[8][4];
#pragma unroll
        for (int j = 0; j < 8; j++)
#pragma unroll
            for (int e = 0; e < 4; e++) s[j][e] = 0.f;

#pragma unroll
        for (int jj = 0; jj < 4; jj++) {
#pragma unroll
            for (int ks = 0; ks < 4; ks++) {
                uint32_t off = (uint32_t)((16 * jj + k_row) * ROWB + 32 * ks + k_col);
                uint32_t bh0, bh1, bh2, bh3;
                LDSM_X4(bh0, bh1, bh2, bh3, xh + off);
                mma16816(s[2 * jj],     qhi[ks], bh0, bh1);
                mma16816(s[2 * jj + 1], qhi[ks], bh2, bh3);
            }
        }

        // ---- P = 2^s, accumulate row sums (no max, no rescale) ----
#pragma unroll
        for (int j = 0; j < 8; j++) {
            s[j][0] = ex2f(s[j][0]);
            s[j][1] = ex2f(s[j][1]);
            s[j][2] = ex2f(s[j][2]);
            s[j][3] = ex2f(s[j][3]);
            l0 += s[j][0] + s[j][1];
            l1 += s[j][2] + s[j][3];
        }

        // ---- P fragments: fp16 hi only ----
        uint32_t phi[4][4];
#pragma unroll
        for (int ks = 0; ks < 4; ks++) {
            int t0 = 2 * ks, t1 = 2 * ks + 1;
            phi[ks][0] = pack_h2(s[t0][0], s[t0][1]);
            phi[ks][1] = pack_h2(s[t0][2], s[t0][3]);
            phi[ks][2] = pack_h2(s[t1][0], s[t1][1]);
            phi[ks][3] = pack_h2(s[t1][2], s[t1][3]);
        }

        // ---- T += Phi.Xhi  (1-pass) ----
#pragma unroll
        for (int jj = 0; jj < 4; jj++) {
#pragma unroll
            for (int ks = 0; ks < 4; ks++) {
                uint32_t off = (uint32_t)((16 * ks + v_row) * ROWB + 32 * jj + v_col);
                uint32_t bh0, bh1, bh2, bh3;
                LDSM_X4_T(bh0, bh1, bh2, bh3, xh + off);
                mma16816(O[2 * jj],     phi[ks], bh0, bh1);
                mma16816(O[2 * jj + 1], phi[ks], bh2, bh3);
            }
        }
    }

    // ---- Deferred l-reduction (quad lanes hold disjoint columns of a row) ----
    l0 += __shfl_xor_sync(0xffffffffu, l0, 1);
    l0 += __shfl_xor_sync(0xffffffffu, l0, 2);
    l1 += __shfl_xor_sync(0xffffffffu, l1, 1);
    l1 += __shfl_xor_sync(0xffffffffu, l1, 2);

    // ---- Epilogue: G = (T/l).Mhi + (T/l).Mlo  (2-pass, hi-only T) ----
    const float i0 = 1.f / l0, i1 = 1.f / l1;
    uint32_t thi[4][4];
#pragma unroll
    for (int ks = 0; ks < 4; ks++) {
        int t0 = 2 * ks, t1 = 2 * ks + 1;
        thi[ks][0] = pack_h2(O[t0][0] * i0, O[t0][1] * i0);
        thi[ks][1] = pack_h2(O[t0][2] * i1, O[t0][3] * i1);
        thi[ks][2] = pack_h2(O[t1][0] * i0, O[t1][1] * i0);
        thi[ks][3] = pack_h2(O[t1][2] * i1, O[t1][3] * i1);
    }

    CP_WAIT(0);
    __syncthreads();  // M_vd visible to all threads

    float gacc[8][4];
#pragma unroll
    for (int j = 0; j < 8; j++)
#pragma unroll
        for (int e = 0; e < 4; e++) gacc[j][e] = 0.f;

    {
        const uint32_t mh = smb + AT_MH;
        const uint32_t ml = smb + AT_ML;
#pragma unroll
        for (int jj = 0; jj < 4; jj++) {
#pragma unroll
            for (int ks = 0; ks < 4; ks++) {
                uint32_t off = (uint32_t)((16 * ks + v_row) * ROWB + 32 * jj + v_col);
                uint32_t bh0, bh1, bh2, bh3, bl0, bl1, bl2, bl3;
                LDSM_X4_T(bh0, bh1, bh2, bh3, mh + off);
                LDSM_X4_T(bl0, bl1, bl2, bl3, ml + off);
                mma16816(gacc[2 * jj],     thi[ks], bh0, bh1);
                mma16816(gacc[2 * jj],     thi[ks], bl0, bl1);
                mma16816(gacc[2 * jj + 1], thi[ks], bh2, bh3);
                mma16816(gacc[2 * jj + 1], thi[ks], bl2, bl3);
            }
        }
    }

    float* Gg = g_gate[br] + ((size_t)b * Nn + qt * 64) * 64;
#pragma unroll
    for (int j = 0; j < 8; j++) {
        int col = 8 * j + 2 * q4;
        *(float2*)(Gg + (size_t)r0 * 64 + col)       = make_float2(gacc[j][0], gacc[j][1]);
        *(float2*)(Gg + (size_t)(r0 + 8) * 64 + col) = make_float2(gacc[j][2], gacc[j][3]);
    }
}

// ---------------------------------------------------------------------------
// Kernel 3: elementwise gate. out = x * sigmoid(gt + gs + bdt + bds).
// ---------------------------------------------------------------------------
__global__ __launch_bounds__(256) void gate_kernel(
    const float* __restrict__ x,
    const float* __restrict__ bdt, const float* __restrict__ bds,
    float* __restrict__ out)
{
    __shared__ float bias[64];
    if (threadIdx.x < 64) bias[threadIdx.x] = bdt[threadIdx.x] + bds[threadIdx.x];
    __syncthreads();

    const size_t i = ((size_t)blockIdx.x * 256 + threadIdx.x) * 4;
    const int c = (int)(i & 63);

    float4 xv = *(const float4*)(x + i);
    float4 g0 = *(const float4*)(g_gate[0] + i);
    float4 g1 = *(const float4*)(g_gate[1] + i);
    float4 ov;
    ov.x = xv.x / (1.f + __expf(-(g0.x + g1.x + bias[c + 0])));
    ov.y = xv.y / (1.f + __expf(-(g0.y + g1.y + bias[c + 1])));
    ov.z = xv.z / (1.f + __expf(-(g0.z + g1.z + bias[c + 2])));
    ov.w = xv.w / (1.f + __expf(-(g0.w + g1.w + bias[c + 3])));
    *(float4*)(out + i) = ov;
}

// ---------------------------------------------------------------------------
extern "C" void kernel_launch(void* const* d_in, const int* in_sizes, int n_in,
                              void* d_out, int out_size)
{
    const float* x   = (const float*)d_in[0];
    const float* Wqt = (const float*)d_in[1];
    const float* Wkt = (const float*)d_in[2];
    const float* Wvt = (const float*)d_in[3];
    const float* Wqs = (const float*)d_in[4];
    const float* Wks = (const float*)d_in[5];
    const float* Wvs = (const float*)d_in[6];
    const float* Wdt = (const float*)d_in[7];
    const float* bdt = (const float*)d_in[8];
    const float* Wds = (const float*)d_in[9];
    const float* bds = (const float*)d_in[10];
    float* out = (float*)d_out;

    cudaFuncSetAttribute(attn_kernel, cudaFuncAttributeMaxDynamicSharedMemorySize, AT_SMEM);

    mm_w_kernel<<<4, 256>>>(Wqt, Wkt, Wqs, Wks, Wvt, Wdt, Wvs, Wds);

    xsplit_kernel<<<TOK * Dd / 1024, 256>>>(x);

    dim3 g2(8, Bb, 2);
    attn_kernel<<<g2, 128, AT_SMEM>>>();

    gate_kernel<<<TOK * Dd / 1024, 256>>>(x, bdt, bds, out);
}

// round 16
// speedup vs baseline: 1.4501x; 1.4501x over previous
#include <cuda_runtime.h>
#include <cuda_fp16.h>
#include <math.h>
#include <stdint.h>

#define Bb 256
#define Nn 512
#define Dd 64
#define TOK (Bb * Nn)        // 131072 tokens
#define TILES (TOK / 64)     // 2048 token tiles
#define SPITCH 72            // smem pitch (fp16): 144B, ldmatrix conflict-free
#define ROWB (SPITCH * 2)    // 144 bytes per smem row
#define TILEB (64 * ROWB)    // 9216 bytes per 64x64 fp16 tile
#define FPAD 68              // fp32 smem pitch

// ---------------------------------------------------------------------------
// Global scratch (allocation-free rule: __device__ globals).
// ---------------------------------------------------------------------------
__device__ __half g_xhi[TOK * Dd];        // x split (fp16 hi/lo)
__device__ __half g_xlo[TOK * Dd];        // lo used only by the Q' prologue
__device__ float  g_gate[2][TOK * Dd];    // gate partial = (P.x).M_vd [br]
__device__ __half g_whi[4][4096];         // M_qk[2] (log2e-scaled), M_vd[2] hi
__device__ __half g_wlo[4][4096];         // split lo

// ---------------------------------------------------------------------------
// Helpers
// ---------------------------------------------------------------------------
__device__ __forceinline__ uint32_t smem_u32(const void* p) {
    uint32_t a;
    asm("{ .reg .u64 t; cvta.to.shared.u64 t, %1; cvt.u32.u64 %0, t; }" : "=r"(a) : "l"(p));
    return a;
}
__device__ __forceinline__ uint32_t ex2_h2(uint32_t v) {
    uint32_t r;
    asm("ex2.approx.f16x2 %0, %1;" : "=r"(r) : "r"(v));
    return r;
}
__device__ __forceinline__ uint32_t pack_h2(float a, float b) {
    __half2 t = __floats2half2_rn(a, b);
    return *(uint32_t*)&t;
}
__device__ __forceinline__ void split_h(float x, float& hi, float& lo) {
    hi = __half2float(__float2half_rn(x));
    lo = x - hi;
}
__device__ __forceinline__ void split_pack2(float a, float b, uint32_t& h, uint32_t& l) {
    float ha, la, hb, lb;
    split_h(a, ha, la);
    split_h(b, hb, lb);
    h = pack_h2(ha, hb);
    l = pack_h2(la, lb);
}

#define LDSM_X4(r0, r1, r2, r3, addr) \
    asm volatile("ldmatrix.sync.aligned.m8n8.x4.shared.b16 {%0,%1,%2,%3}, [%4];" \
                 : "=r"(r0), "=r"(r1), "=r"(r2), "=r"(r3) : "r"(addr))
#define LDSM_X4_T(r0, r1, r2, r3, addr) \
    asm volatile("ldmatrix.sync.aligned.m8n8.x4.trans.shared.b16 {%0,%1,%2,%3}, [%4];" \
                 : "=r"(r0), "=r"(r1), "=r"(r2), "=r"(r3) : "r"(addr))

#define CP_ASYNC16(dst, src) \
    asm volatile("cp.async.cg.shared.global [%0], [%1], 16;" :: "r"(dst), "l"(src))
#define CP_COMMIT() asm volatile("cp.async.commit_group;")
#define CP_WAIT(n)  asm volatile("cp.async.wait_group %0;" :: "n"(n))

__device__ __forceinline__ void mma16816(float c[4], const uint32_t a[4],
                                         uint32_t b0, uint32_t b1) {
    asm volatile(
        "mma.sync.aligned.m16n8k16.row.col.f32.f16.f16.f32 "
        "{%0,%1,%2,%3}, {%4,%5,%6,%7}, {%8,%9}, {%0,%1,%2,%3};"
        : "+f"(c[0]), "+f"(c[1]), "+f"(c[2]), "+f"(c[3])
        : "r"(a[0]), "r"(a[1]), "r"(a[2]), "r"(a[3]), "r"(b0), "r"(b1));
}

// cp.async a 64x64 fp16 tile (row-major, 128B rows) into pitch-144B smem.
__device__ __forceinline__ void cp_tile(uint32_t smem_dst, const __half* src,
                                        int tid, int nthreads) {
    for (int i = tid; i < 512; i += nthreads) {
        uint32_t d = smem_dst + (uint32_t)((i >> 3) * ROWB + (i & 7) * 16);
        CP_ASYNC16(d, src + i * 8);
    }
}

// ---------------------------------------------------------------------------
// Kernel 0: precompute fused weight products (fp32), split to fp16 hi/lo.
//   idx 0,1: M_qk[br] = (0.125*log2e) * Wq * Wk^T   (scores in log2-domain)
//   idx 2,3: M_vd[br] = Wv * Wd
// ---------------------------------------------------------------------------
__global__ __launch_bounds__(256) void mm_w_kernel(
    const float* __restrict__ Wqt, const float* __restrict__ Wkt,
    const float* __restrict__ Wqs, const float* __restrict__ Wks,
    const float* __restrict__ Wvt, const float* __restrict__ Wdt,
    const float* __restrict__ Wvs, const float* __restrict__ Wds)
{
    __shared__ float As[64][FPAD];
    __shared__ float Bs[64][FPAD];

    const int idx = blockIdx.x;
    const int tid = threadIdx.x;
    const int ty = tid >> 4;
    const int tx = tid & 15;

    const float LOG2E = 1.4426950408889634f;
    const float* A;
    const float* B;
    bool transB;
    float sc;
    switch (idx) {
        case 0:  A = Wqt; B = Wkt; transB = true;  sc = 0.125f * LOG2E; break;
        case 1:  A = Wqs; B = Wks; transB = true;  sc = 0.125f * LOG2E; break;
        case 2:  A = Wvt; B = Wdt; transB = false; sc = 1.0f;           break;
        default: A = Wvs; B = Wds; transB = false; sc = 1.0f;           break;
    }

    for (int i = tid; i < 1024; i += 256) {
        int r = i >> 4;
        int c = (i & 15) << 2;
        *(float4*)&As[r][c] = *(const float4*)(A + r * 64 + c);
        float4 bv = *(const float4*)(B + r * 64 + c);
        if (transB) {
            Bs[c + 0][r] = bv.x;
            Bs[c + 1][r] = bv.y;
            Bs[c + 2][r] = bv.z;
            Bs[c + 3][r] = bv.w;
        } else {
            *(float4*)&Bs[r][c] = bv;
        }
    }
    __syncthreads();

    float acc[4][4] = {};
#pragma unroll
    for (int k = 0; k < 64; k += 4) {
        float a[4][4];
#pragma unroll
        for (int i = 0; i < 4; i++)
            *(float4*)a[i] = *(const float4*)&As[4 * ty + i][k];
#pragma unroll
        for (int kk = 0; kk < 4; kk++) {
            float4 b4 = *(const float4*)&Bs[k + kk][4 * tx];
#pragma unroll
            for (int i = 0; i < 4; i++) {
                acc[i][0] += a[i][kk] * b4.x;
                acc[i][1] += a[i][kk] * b4.y;
                acc[i][2] += a[i][kk] * b4.z;
                acc[i][3] += a[i][kk] * b4.w;
            }
        }
    }

#pragma unroll
    for (int i = 0; i < 4; i++) {
        uint2 h, l;
        split_pack2(acc[i][0] * sc, acc[i][1] * sc, h.x, l.x);
        split_pack2(acc[i][2] * sc, acc[i][3] * sc, h.y, l.y);
        int off = (4 * ty + i) * 64 + 4 * tx;
        *(uint2*)&g_whi[idx][off] = h;
        *(uint2*)&g_wlo[idx][off] = l;
    }
}

// ---------------------------------------------------------------------------
// Kernel 1: split x into fp16 hi/lo (pure streaming).
// ---------------------------------------------------------------------------
__global__ __launch_bounds__(256) void xsplit_kernel(const float* __restrict__ x)
{
    const size_t i = ((size_t)blockIdx.x * 256 + threadIdx.x) * 4;
    float4 v = *(const float4*)(x + i);
    uint2 h, l;
    split_pack2(v.x, v.y, h.x, l.x);
    split_pack2(v.z, v.w, h.y, l.y);
    *(uint2*)(g_xhi + i) = h;
    *(uint2*)(g_xlo + i) = l;
}

// ---------------------------------------------------------------------------
// Kernel 2: fused Q'-projection + flash attention + output projection.
// Precision: Q' prologue 3-pass; S 1-pass; T 1-pass; epilogue 2-pass.
// P computed with ex2.approx.f16x2 directly in fp16 (halves MUFU count; P is
// fp16-quantized anyway, and l sums the same perturbed values so the
// normalization cancels common-mode error). Row sums in fp32 via cvt.
// 4-stage Xhi ring (wait_group(2) steady -> 2 tiles of latency slack),
// M_qk/M_vd in fixed slots 4/5 (M_vd committed at kt=5). Unnormalized
// P = 2^s; deferred l. grid (8,256,2), 128 thr, 4 blocks/SM. MMA/warp = 672.
// Dynamic smem = 6 tiles = 55296B.
// ---------------------------------------------------------------------------
#define AT_STG(s) ((s) * TILEB)
#define AT_MH (4 * TILEB)
#define AT_ML (5 * TILEB)
#define AT_SMEM (6 * TILEB)

__global__ __launch_bounds__(128, 4) void attn_kernel()
{
    extern __shared__ char sm[];
    const uint32_t smb = smem_u32(sm);

    const int tid  = threadIdx.x;
    const int wid  = tid >> 5;
    const int lane = tid & 31;
    const int g    = lane >> 2;
    const int q4   = lane & 3;
    const int qt = blockIdx.x;
    const int b  = blockIdx.y;
    const int br = blockIdx.z;

    const __half* Xg_h = g_xhi + (size_t)b * Nn * 64;
    const __half* Xg_l = g_xlo + (size_t)b * Nn * 64;

    // G0: M_qk (hi/lo).  G1: x0.  G2: x1.  G3: x2.
    cp_tile(smb + AT_MH, g_whi[br], tid, 128);
    cp_tile(smb + AT_ML, g_wlo[br], tid, 128);
    CP_COMMIT();
    cp_tile(smb + AT_STG(0), Xg_h, tid, 128);
    CP_COMMIT();
    cp_tile(smb + AT_STG(1), Xg_h + 4096, tid, 128);
    CP_COMMIT();
    cp_tile(smb + AT_STG(2), Xg_h + 8192, tid, 128);
    CP_COMMIT();

    // x(qt) A-fragments from gmem (overlaps the async loads).
    const __half* XQh = Xg_h + (size_t)qt * 4096;
    const __half* XQl = Xg_l + (size_t)qt * 4096;
    const int r0 = wid * 16 + g;
    uint32_t xqhi[4][4], xqlo[4][4];
#pragma unroll
    for (int ks = 0; ks < 4; ks++) {
        int base = 16 * ks + 2 * q4;
        xqhi[ks][0] = *(const uint32_t*)(XQh + (size_t)r0 * 64 + base);
        xqhi[ks][1] = *(const uint32_t*)(XQh + (size_t)(r0 + 8) * 64 + base);
        xqhi[ks][2] = *(const uint32_t*)(XQh + (size_t)r0 * 64 + base + 8);
        xqhi[ks][3] = *(const uint32_t*)(XQh + (size_t)(r0 + 8) * 64 + base + 8);
        xqlo[ks][0] = *(const uint32_t*)(XQl + (size_t)r0 * 64 + base);
        xqlo[ks][1] = *(const uint32_t*)(XQl + (size_t)(r0 + 8) * 64 + base);
        xqlo[ks][2] = *(const uint32_t*)(XQl + (size_t)r0 * 64 + base + 8);
        xqlo[ks][3] = *(const uint32_t*)(XQl + (size_t)(r0 + 8) * 64 + base + 8);
    }

    const int k_row = (lane & 7) + ((lane >> 4) << 3);
    const int k_col = ((lane >> 3) & 1) << 4;
    const int v_row = (lane & 7) + (((lane >> 3) & 1) << 3);
    const int v_col = (lane >> 4) << 4;

    // ---- Prologue GEMM: Q' = x(qt) . M_qk (3-pass; hi operand exact) ----
    CP_WAIT(3);        // M_qk resident (x0..x2 may still be in flight)
    __syncthreads();

    uint32_t qhi[4][4];
    {
        const uint32_t mh = smb + AT_MH;
        const uint32_t ml = smb + AT_ML;
        float qacc[8][4];
#pragma unroll
        for (int j = 0; j < 8; j++)
#pragma unroll
            for (int e = 0; e < 4; e++) qacc[j][e] = 0.f;

#pragma unroll
        for (int jj = 0; jj < 4; jj++) {
#pragma unroll
            for (int ks = 0; ks < 4; ks++) {
                uint32_t off = (uint32_t)((16 * ks + v_row) * ROWB + 32 * jj + v_col);
                uint32_t bh0, bh1, bh2, bh3, bl0, bl1, bl2, bl3;
                LDSM_X4_T(bh0, bh1, bh2, bh3, mh + off);
                LDSM_X4_T(bl0, bl1, bl2, bl3, ml + off);
                mma16816(qacc[2 * jj],     xqhi[ks], bh0, bh1);
                mma16816(qacc[2 * jj],     xqlo[ks], bh0, bh1);
                mma16816(qacc[2 * jj],     xqhi[ks], bl0, bl1);
                mma16816(qacc[2 * jj + 1], xqhi[ks], bh2, bh3);
                mma16816(qacc[2 * jj + 1], xqlo[ks], bh2, bh3);
                mma16816(qacc[2 * jj + 1], xqhi[ks], bl2, bl3);
            }
        }
        // A-fragment repack, hi only (S is 1-pass).
#pragma unroll
        for (int ks = 0; ks < 4; ks++) {
            int t0 = 2 * ks, t1 = 2 * ks + 1;
            qhi[ks][0] = pack_h2(qacc[t0][0], qacc[t0][1]);
            qhi[ks][1] = pack_h2(qacc[t0][2], qacc[t0][3]);
            qhi[ks][2] = pack_h2(qacc[t1][0], qacc[t1][1]);
            qhi[ks][3] = pack_h2(qacc[t1][2], qacc[t1][3]);
        }
    }

    float O[8][4];
#pragma unroll
    for (int j = 0; j < 8; j++)
#pragma unroll
        for (int e = 0; e < 4; e++) O[j][e] = 0.f;
    float l0 = 0.f, l1 = 0.f;   // unnormalized row sums (quad-partial)

    for (int kt = 0; kt < 8; kt++) {
        if (kt < 7) { CP_WAIT(2); } else { CP_WAIT(1); }
        __syncthreads();  // stage kt visible; readers of slot (kt+3)%4 retired

        if (kt < 5) {
            cp_tile(smb + AT_STG((kt + 3) & 3), Xg_h + (size_t)(kt + 3) * 4096, tid, 128);
            CP_COMMIT();
        } else if (kt == 5) {
            // M_qk fully consumed in the prologue; stream M_vd into its slots.
            cp_tile(smb + AT_MH, g_whi[2 + br], tid, 128);
            cp_tile(smb + AT_ML, g_wlo[2 + br], tid, 128);
            CP_COMMIT();
        }

        const uint32_t xh = smb + AT_STG(kt & 3);

        // ---- S~ = Qhi.Xhi  (1-pass, log2 scores) ----
        float s[8][4];
#pragma unroll
        for (int j = 0; j < 8; j++)
#pragma unroll
            for (int e = 0; e < 4; e++) s[j][e] = 0.f;

#pragma unroll
        for (int jj = 0; jj < 4; jj++) {
#pragma unroll
            for (int ks = 0; ks < 4; ks++) {
                uint32_t off = (uint32_t)((16 * jj + k_row) * ROWB + 32 * ks + k_col);
                uint32_t bh0, bh1, bh2, bh3;
                LDSM_X4(bh0, bh1, bh2, bh3, xh + off);
                mma16816(s[2 * jj],     qhi[ks], bh0, bh1);
                mma16816(s[2 * jj + 1], qhi[ks], bh2, bh3);
            }
        }

        // ---- P = 2^s via ex2.approx.f16x2; fp32 row sums from the same P ----
        uint32_t phi[4][4];
#pragma unroll
        for (int ks = 0; ks < 4; ks++) {
            int t0 = 2 * ks, t1 = 2 * ks + 1;
            phi[ks][0] = ex2_h2(pack_h2(s[t0][0], s[t0][1]));
            phi[ks][1] = ex2_h2(pack_h2(s[t0][2], s[t0][3]));
            phi[ks][2] = ex2_h2(pack_h2(s[t1][0], s[t1][1]));
            phi[ks][3] = ex2_h2(pack_h2(s[t1][2], s[t1][3]));
            float2 f0 = __half22float2(*(__half2*)&phi[ks][0]);
            float2 f1 = __half22float2(*(__half2*)&phi[ks][1]);
            float2 f2 = __half22float2(*(__half2*)&phi[ks][2]);
            float2 f3 = __half22float2(*(__half2*)&phi[ks][3]);
            l0 += f0.x + f0.y + f2.x + f2.y;
            l1 += f1.x + f1.y + f3.x + f3.y;
        }

        // ---- T += Phi.Xhi  (1-pass) ----
#pragma unroll
        for (int jj = 0; jj < 4; jj++) {
#pragma unroll
            for (int ks = 0; ks < 4; ks++) {
                uint32_t off = (uint32_t)((16 * ks + v_row) * ROWB + 32 * jj + v_col);
                uint32_t bh0, bh1, bh2, bh3;
                LDSM_X4_T(bh0, bh1, bh2, bh3, xh + off);
                mma16816(O[2 * jj],     phi[ks], bh0, bh1);
                mma16816(O[2 * jj + 1], phi[ks], bh2, bh3);
            }
        }
    }

    // ---- Deferred l-reduction (quad lanes hold disjoint columns of a row) ----
    l0 += __shfl_xor_sync(0xffffffffu, l0, 1);
    l0 += __shfl_xor_sync(0xffffffffu, l0, 2);
    l1 += __shfl_xor_sync(0xffffffffu, l1, 1);
    l1 += __shfl_xor_sync(0xffffffffu, l1, 2);

    // ---- Epilogue: G = (T/l).Mhi + (T/l).Mlo  (2-pass, hi-only T) ----
    const float i0 = 1.f / l0, i1 = 1.f / l1;
    uint32_t thi[4][4];
#pragma unroll
    for (int ks = 0; ks < 4; ks++) {
        int t0 = 2 * ks, t1 = 2 * ks + 1;
        thi[ks][0] = pack_h2(O[t0][0] * i0, O[t0][1] * i0);
        thi[ks][1] = pack_h2(O[t0][2] * i1, O[t0][3] * i1);
        thi[ks][2] = pack_h2(O[t1][0] * i0, O[t1][1] * i0);
        thi[ks][3] = pack_h2(O[t1][2] * i1, O[t1][3] * i1);
    }

    CP_WAIT(0);
    __syncthreads();  // M_vd visible to all threads

    float gacc[8][4];
#pragma unroll
    for (int j = 0; j < 8; j++)
#pragma unroll
        for (int e = 0; e < 4; e++) gacc[j][e] = 0.f;

    {
        const uint32_t mh = smb + AT_MH;
        const uint32_t ml = smb + AT_ML;
#pragma unroll
        for (int jj = 0; jj < 4; jj++) {
#pragma unroll
            for (int ks = 0; ks < 4; ks++) {
                uint32_t off = (uint32_t)((16 * ks + v_row) * ROWB + 32 * jj + v_col);
                uint32_t bh0, bh1, bh2, bh3, bl0, bl1, bl2, bl3;
                LDSM_X4_T(bh0, bh1, bh2, bh3, mh + off);
                LDSM_X4_T(bl0, bl1, bl2, bl3, ml + off);
                mma16816(gacc[2 * jj],     thi[ks], bh0, bh1);
                mma16816(gacc[2 * jj],     thi[ks], bl0, bl1);
                mma16816(gacc[2 * jj + 1], thi[ks], bh2, bh3);
                mma16816(gacc[2 * jj + 1], thi[ks], bl2, bl3);
            }
        }
    }

    float* Gg = g_gate[br] + ((size_t)b * Nn + qt * 64) * 64;
#pragma unroll
    for (int j = 0; j < 8; j++) {
        int col = 8 * j + 2 * q4;
        *(float2*)(Gg + (size_t)r0 * 64 + col)       = make_float2(gacc[j][0], gacc[j][1]);
        *(float2*)(Gg + (size_t)(r0 + 8) * 64 + col) = make_float2(gacc[j][2], gacc[j][3]);
    }
}

// ---------------------------------------------------------------------------
// Kernel 3: elementwise gate. out = x * sigmoid(gt + gs + bdt + bds).
// ---------------------------------------------------------------------------
__global__ __launch_bounds__(256) void gate_kernel(
    const float* __restrict__ x,
    const float* __restrict__ bdt, const float* __restrict__ bds,
    float* __restrict__ out)
{
    __shared__ float bias[64];
    if (threadIdx.x < 64) bias[threadIdx.x] = bdt[threadIdx.x] + bds[threadIdx.x];
    __syncthreads();

    const size_t i = ((size_t)blockIdx.x * 256 + threadIdx.x) * 4;
    const int c = (int)(i & 63);

    float4 xv = *(const float4*)(x + i);
    float4 g0 = *(const float4*)(g_gate[0] + i);
    float4 g1 = *(const float4*)(g_gate[1] + i);
    float4 ov;
    ov.x = xv.x / (1.f + __expf(-(g0.x + g1.x + bias[c + 0])));
    ov.y = xv.y / (1.f + __expf(-(g0.y + g1.y + bias[c + 1])));
    ov.z = xv.z / (1.f + __expf(-(g0.z + g1.z + bias[c + 2])));
    ov.w = xv.w / (1.f + __expf(-(g0.w + g1.w + bias[c + 3])));
    *(float4*)(out + i) = ov;
}

// ---------------------------------------------------------------------------
extern "C" void kernel_launch(void* const* d_in, const int* in_sizes, int n_in,
                              void* d_out, int out_size)
{
    const float* x   = (const float*)d_in[0];
    const float* Wqt = (const float*)d_in[1];
    const float* Wkt = (const float*)d_in[2];
    const float* Wvt = (const float*)d_in[3];
    const float* Wqs = (const float*)d_in[4];
    const float* Wks = (const float*)d_in[5];
    const float* Wvs = (const float*)d_in[6];
    const float* Wdt = (const float*)d_in[7];
    const float* bdt = (const float*)d_in[8];
    const float* Wds = (const float*)d_in[9];
    const float* bds = (const float*)d_in[10];
    float* out = (float*)d_out;

    cudaFuncSetAttribute(attn_kernel, cudaFuncAttributeMaxDynamicSharedMemorySize, AT_SMEM);

    mm_w_kernel<<<4, 256>>>(Wqt, Wkt, Wqs, Wks, Wvt, Wdt, Wvs, Wds);

    xsplit_kernel<<<TOK * Dd / 1024, 256>>>(x);

    dim3 g2(8, Bb, 2);
    attn_kernel<<<g2, 128, AT_SMEM>>>();

    gate_kernel<<<TOK * Dd / 1024, 256>>>(x, bdt, bds, out);
}

// round 17
// speedup vs baseline: 1.5192x; 1.0477x over previous
#include <cuda_runtime.h>
#include <cuda_fp16.h>
#include <math.h>
#include <stdint.h>

#define Bb 256
#define Nn 512
#define Dd 64
#define TOK (Bb * Nn)        // 131072 tokens
#define SPITCH 72            // smem pitch (fp16): 144B, ldmatrix conflict-free
#define ROWB (SPITCH * 2)    // 144 bytes per smem row
#define TILEB (64 * ROWB)    // 9216 bytes per 64x64 fp16 tile
#define FPAD 68              // fp32 smem pitch

// ---------------------------------------------------------------------------
// Global scratch (allocation-free rule: __device__ globals).
// ---------------------------------------------------------------------------
__device__ __half g_xhi[TOK * Dd];        // x rounded to fp16 (streamed in attn)
__device__ float  g_gate[2][TOK * Dd];    // gate partial = (P.x).M_vd [br]
__device__ __half g_whi[4][4096];         // M_qk[2] (log2e-scaled), M_vd[2] hi
__device__ __half g_wlo[4][4096];         // split lo

// ---------------------------------------------------------------------------
// Helpers
// ---------------------------------------------------------------------------
__device__ __forceinline__ uint32_t smem_u32(const void* p) {
    uint32_t a;
    asm("{ .reg .u64 t; cvta.to.shared.u64 t, %1; cvt.u32.u64 %0, t; }" : "=r"(a) : "l"(p));
    return a;
}
__device__ __forceinline__ uint32_t ex2_h2(uint32_t v) {
    uint32_t r;
    asm("ex2.approx.f16x2 %0, %1;" : "=r"(r) : "r"(v));
    return r;
}
__device__ __forceinline__ uint32_t pack_h2(float a, float b) {
    __half2 t = __floats2half2_rn(a, b);
    return *(uint32_t*)&t;
}
__device__ __forceinline__ void split_h(float x, float& hi, float& lo) {
    hi = __half2float(__float2half_rn(x));
    lo = x - hi;
}
__device__ __forceinline__ void split_pack2(float a, float b, uint32_t& h, uint32_t& l) {
    float ha, la, hb, lb;
    split_h(a, ha, la);
    split_h(b, hb, lb);
    h = pack_h2(ha, hb);
    l = pack_h2(la, lb);
}

#define LDSM_X4(r0, r1, r2, r3, addr) \
    asm volatile("ldmatrix.sync.aligned.m8n8.x4.shared.b16 {%0,%1,%2,%3}, [%4];" \
                 : "=r"(r0), "=r"(r1), "=r"(r2), "=r"(r3) : "r"(addr))
#define LDSM_X4_T(r0, r1, r2, r3, addr) \
    asm volatile("ldmatrix.sync.aligned.m8n8.x4.trans.shared.b16 {%0,%1,%2,%3}, [%4];" \
                 : "=r"(r0), "=r"(r1), "=r"(r2), "=r"(r3) : "r"(addr))

#define CP_ASYNC16(dst, src) \
    asm volatile("cp.async.cg.shared.global [%0], [%1], 16;" :: "r"(dst), "l"(src))
#define CP_COMMIT() asm volatile("cp.async.commit_group;")
#define CP_WAIT(n)  asm volatile("cp.async.wait_group %0;" :: "n"(n))

__device__ __forceinline__ void mma16816(float c[4], const uint32_t a[4],
                                         uint32_t b0, uint32_t b1) {
    asm volatile(
        "mma.sync.aligned.m16n8k16.row.col.f32.f16.f16.f32 "
        "{%0,%1,%2,%3}, {%4,%5,%6,%7}, {%8,%9}, {%0,%1,%2,%3};"
        : "+f"(c[0]), "+f"(c[1]), "+f"(c[2]), "+f"(c[3])
        : "r"(a[0]), "r"(a[1]), "r"(a[2]), "r"(a[3]), "r"(b0), "r"(b1));
}

// cp.async a 64x64 fp16 tile (row-major, 128B rows) into pitch-144B smem.
__device__ __forceinline__ void cp_tile(uint32_t smem_dst, const __half* src,
                                        int tid, int nthreads) {
    for (int i = tid; i < 512; i += nthreads) {
        uint32_t d = smem_dst + (uint32_t)((i >> 3) * ROWB + (i & 7) * 16);
        CP_ASYNC16(d, src + i * 8);
    }
}

// ---------------------------------------------------------------------------
// Kernel 0: precompute fused weight products (fp32), split to fp16 hi/lo.
//   idx 0,1: M_qk[br] = (0.125*log2e) * Wq * Wk^T   (scores in log2-domain)
//   idx 2,3: M_vd[br] = Wv * Wd
// ---------------------------------------------------------------------------
__global__ __launch_bounds__(256) void mm_w_kernel(
    const float* __restrict__ Wqt, const float* __restrict__ Wkt,
    const float* __restrict__ Wqs, const float* __restrict__ Wks,
    const float* __restrict__ Wvt, const float* __restrict__ Wdt,
    const float* __restrict__ Wvs, const float* __restrict__ Wds)
{
    __shared__ float As[64][FPAD];
    __shared__ float Bs[64][FPAD];

    const int idx = blockIdx.x;
    const int tid = threadIdx.x;
    const int ty = tid >> 4;
    const int tx = tid & 15;

    const float LOG2E = 1.4426950408889634f;
    const float* A;
    const float* B;
    bool transB;
    float sc;
    switch (idx) {
        case 0:  A = Wqt; B = Wkt; transB = true;  sc = 0.125f * LOG2E; break;
        case 1:  A = Wqs; B = Wks; transB = true;  sc = 0.125f * LOG2E; break;
        case 2:  A = Wvt; B = Wdt; transB = false; sc = 1.0f;           break;
        default: A = Wvs; B = Wds; transB = false; sc = 1.0f;           break;
    }

    for (int i = tid; i < 1024; i += 256) {
        int r = i >> 4;
        int c = (i & 15) << 2;
        *(float4*)&As[r][c] = *(const float4*)(A + r * 64 + c);
        float4 bv = *(const float4*)(B + r * 64 + c);
        if (transB) {
            Bs[c + 0][r] = bv.x;
            Bs[c + 1][r] = bv.y;
            Bs[c + 2][r] = bv.z;
            Bs[c + 3][r] = bv.w;
        } else {
            *(float4*)&Bs[r][c] = bv;
        }
    }
    __syncthreads();

    float acc[4][4] = {};
#pragma unroll
    for (int k = 0; k < 64; k += 4) {
        float a[4][4];
#pragma unroll
        for (int i = 0; i < 4; i++)
            *(float4*)a[i] = *(const float4*)&As[4 * ty + i][k];
#pragma unroll
        for (int kk = 0; kk < 4; kk++) {
            float4 b4 = *(const float4*)&Bs[k + kk][4 * tx];
#pragma unroll
            for (int i = 0; i < 4; i++) {
                acc[i][0] += a[i][kk] * b4.x;
                acc[i][1] += a[i][kk] * b4.y;
                acc[i][2] += a[i][kk] * b4.z;
                acc[i][3] += a[i][kk] * b4.w;
            }
        }
    }

#pragma unroll
    for (int i = 0; i < 4; i++) {
        uint2 h, l;
        split_pack2(acc[i][0] * sc, acc[i][1] * sc, h.x, l.x);
        split_pack2(acc[i][2] * sc, acc[i][3] * sc, h.y, l.y);
        int off = (4 * ty + i) * 64 + 4 * tx;
        *(uint2*)&g_whi[idx][off] = h;
        *(uint2*)&g_wlo[idx][off] = l;
    }
}

// ---------------------------------------------------------------------------
// Kernel 1: round x to fp16 hi (lo is recomputed in attn's prologue from fp32).
// ---------------------------------------------------------------------------
__global__ __launch_bounds__(256) void xsplit_kernel(const float* __restrict__ x)
{
    const size_t i = ((size_t)blockIdx.x * 256 + threadIdx.x) * 4;
    float4 v = *(const float4*)(x + i);
    uint2 h;
    h.x = pack_h2(v.x, v.y);
    h.y = pack_h2(v.z, v.w);
    *(uint2*)(g_xhi + i) = h;
}

// ---------------------------------------------------------------------------
// Kernel 2: fused Q'-projection + flash attention + output projection.
// 128 q-rows/block, 256 threads (8 warps, 16 rows each), grid (4,256,2).
// Precision: Q' prologue 3-pass (x fragments read fp32 & split in regs);
// S 1-pass; T 1-pass; epilogue 2-pass. P via ex2.approx.f16x2.
// 4-stage Xhi ring; M_qk/M_vd in fixed slots 4/5 (M_vd committed at kt=5).
// Unnormalized P = 2^s; deferred l. 2 blocks/SM (16 warps).
// Dynamic smem = 6 tiles = 55296B.
// ---------------------------------------------------------------------------
#define AT_STG(s) ((s) * TILEB)
#define AT_MH (4 * TILEB)
#define AT_ML (5 * TILEB)
#define AT_SMEM (6 * TILEB)

__global__ __launch_bounds__(256, 2) void attn_kernel(const float* __restrict__ x)
{
    extern __shared__ char sm[];
    const uint32_t smb = smem_u32(sm);

    const int tid  = threadIdx.x;
    const int wid  = tid >> 5;
    const int lane = tid & 31;
    const int g    = lane >> 2;
    const int q4   = lane & 3;
    const int qt = blockIdx.x;   // 0..3, 128 q-rows each
    const int b  = blockIdx.y;
    const int br = blockIdx.z;

    const __half* Xg_h = g_xhi + (size_t)b * Nn * 64;

    // G0: M_qk (hi/lo).  G1: x0.  G2: x1.  G3: x2.
    cp_tile(smb + AT_MH, g_whi[br], tid, 256);
    cp_tile(smb + AT_ML, g_wlo[br], tid, 256);
    CP_COMMIT();
    cp_tile(smb + AT_STG(0), Xg_h, tid, 256);
    CP_COMMIT();
    cp_tile(smb + AT_STG(1), Xg_h + 4096, tid, 256);
    CP_COMMIT();
    cp_tile(smb + AT_STG(2), Xg_h + 8192, tid, 256);
    CP_COMMIT();

    // x(qt) A-fragments: read fp32 x directly, split hi/lo in registers (exact).
    const float* XQ = x + ((size_t)b * Nn + qt * 128) * 64;
    const int r0 = wid * 16 + g;   // 0..127
    uint32_t xqhi[4][4], xqlo[4][4];
#pragma unroll
    for (int ks = 0; ks < 4; ks++) {
        int base = 16 * ks + 2 * q4;
        float2 v0 = *(const float2*)(XQ + (size_t)r0 * 64 + base);
        float2 v1 = *(const float2*)(XQ + (size_t)(r0 + 8) * 64 + base);
        float2 v2 = *(const float2*)(XQ + (size_t)r0 * 64 + base + 8);
        float2 v3 = *(const float2*)(XQ + (size_t)(r0 + 8) * 64 + base + 8);
        split_pack2(v0.x, v0.y, xqhi[ks][0], xqlo[ks][0]);
        split_pack2(v1.x, v1.y, xqhi[ks][1], xqlo[ks][1]);
        split_pack2(v2.x, v2.y, xqhi[ks][2], xqlo[ks][2]);
        split_pack2(v3.x, v3.y, xqhi[ks][3], xqlo[ks][3]);
    }

    const int k_row = (lane & 7) + ((lane >> 4) << 3);
    const int k_col = ((lane >> 3) & 1) << 4;
    const int v_row = (lane & 7) + (((lane >> 3) & 1) << 3);
    const int v_col = (lane >> 4) << 4;

    // ---- Prologue GEMM: Q' = x(qt) . M_qk (3-pass; hi operand exact) ----
    CP_WAIT(3);        // M_qk resident (x0..x2 may still be in flight)
    __syncthreads();

    uint32_t qhi[4][4];
    {
        const uint32_t mh = smb + AT_MH;
        const uint32_t ml = smb + AT_ML;
        float qacc[8][4];
#pragma unroll
        for (int j = 0; j < 8; j++)
#pragma unroll
            for (int e = 0; e < 4; e++) qacc[j][e] = 0.f;

#pragma unroll
        for (int jj = 0; jj < 4; jj++) {
#pragma unroll
            for (int ks = 0; ks < 4; ks++) {
                uint32_t off = (uint32_t)((16 * ks + v_row) * ROWB + 32 * jj + v_col);
                uint32_t bh0, bh1, bh2, bh3, bl0, bl1, bl2, bl3;
                LDSM_X4_T(bh0, bh1, bh2, bh3, mh + off);
                LDSM_X4_T(bl0, bl1, bl2, bl3, ml + off);
                mma16816(qacc[2 * jj],     xqhi[ks], bh0, bh1);
                mma16816(qacc[2 * jj],     xqlo[ks], bh0, bh1);
                mma16816(qacc[2 * jj],     xqhi[ks], bl0, bl1);
                mma16816(qacc[2 * jj + 1], xqhi[ks], bh2, bh3);
                mma16816(qacc[2 * jj + 1], xqlo[ks], bh2, bh3);
                mma16816(qacc[2 * jj + 1], xqhi[ks], bl2, bl3);
            }
        }
        // A-fragment repack, hi only (S is 1-pass).
#pragma unroll
        for (int ks = 0; ks < 4; ks++) {
            int t0 = 2 * ks, t1 = 2 * ks + 1;
            qhi[ks][0] = pack_h2(qacc[t0][0], qacc[t0][1]);
            qhi[ks][1] = pack_h2(qacc[t0][2], qacc[t0][3]);
            qhi[ks][2] = pack_h2(qacc[t1][0], qacc[t1][1]);
            qhi[ks][3] = pack_h2(qacc[t1][2], qacc[t1][3]);
        }
    }

    float O[8][4];
#pragma unroll
    for (int j = 0; j < 8; j++)
#pragma unroll
        for (int e = 0; e < 4; e++) O[j][e] = 0.f;
    float l0 = 0.f, l1 = 0.f;   // unnormalized row sums (quad-partial)

    for (int kt = 0; kt < 8; kt++) {
        if (kt < 7) { CP_WAIT(2); } else { CP_WAIT(1); }
        __syncthreads();  // stage kt visible; readers of slot (kt+3)%4 retired

        if (kt < 5) {
            cp_tile(smb + AT_STG((kt + 3) & 3), Xg_h + (size_t)(kt + 3) * 4096, tid, 256);
            CP_COMMIT();
        } else if (kt == 5) {
            // M_qk fully consumed in the prologue; stream M_vd into its slots.
            cp_tile(smb + AT_MH, g_whi[2 + br], tid, 256);
            cp_tile(smb + AT_ML, g_wlo[2 + br], tid, 256);
            CP_COMMIT();
        }

        const uint32_t xh = smb + AT_STG(kt & 3);

        // ---- S~ = Qhi.Xhi  (1-pass, log2 scores) ----
        float s[8][4];
#pragma unroll
        for (int j = 0; j < 8; j++)
#pragma unroll
            for (int e = 0; e < 4; e++) s[j][e] = 0.f;

#pragma unroll
        for (int jj = 0; jj < 4; jj++) {
#pragma unroll
            for (int ks = 0; ks < 4; ks++) {
                uint32_t off = (uint32_t)((16 * jj + k_row) * ROWB + 32 * ks + k_col);
                uint32_t bh0, bh1, bh2, bh3;
                LDSM_X4(bh0, bh1, bh2, bh3, xh + off);
                mma16816(s[2 * jj],     qhi[ks], bh0, bh1);
                mma16816(s[2 * jj + 1], qhi[ks], bh2, bh3);
            }
        }

        // ---- P = 2^s via ex2.approx.f16x2; fp32 row sums from the same P ----
        uint32_t phi[4][4];
#pragma unroll
        for (int ks = 0; ks < 4; ks++) {
            int t0 = 2 * ks, t1 = 2 * ks + 1;
            phi[ks][0] = ex2_h2(pack_h2(s[t0][0], s[t0][1]));
            phi[ks][1] = ex2_h2(pack_h2(s[t0][2], s[t0][3]));
            phi[ks][2] = ex2_h2(pack_h2(s[t1][0], s[t1][1]));
            phi[ks][3] = ex2_h2(pack_h2(s[t1][2], s[t1][3]));
            float2 f0 = __half22float2(*(__half2*)&phi[ks][0]);
            float2 f1 = __half22float2(*(__half2*)&phi[ks][1]);
            float2 f2 = __half22float2(*(__half2*)&phi[ks][2]);
            float2 f3 = __half22float2(*(__half2*)&phi[ks][3]);
            l0 += f0.x + f0.y + f2.x + f2.y;
            l1 += f1.x + f1.y + f3.x + f3.y;
        }

        // ---- T += Phi.Xhi  (1-pass) ----
#pragma unroll
        for (int jj = 0; jj < 4; jj++) {
#pragma unroll
            for (int ks = 0; ks < 4; ks++) {
                uint32_t off = (uint32_t)((16 * ks + v_row) * ROWB + 32 * jj + v_col);
                uint32_t bh0, bh1, bh2, bh3;
                LDSM_X4_T(bh0, bh1, bh2, bh3, xh + off);
                mma16816(O[2 * jj],     phi[ks], bh0, bh1);
                mma16816(O[2 * jj + 1], phi[ks], bh2, bh3);
            }
        }
    }

    // ---- Deferred l-reduction (quad lanes hold disjoint columns of a row) ----
    l0 += __shfl_xor_sync(0xffffffffu, l0, 1);
    l0 += __shfl_xor_sync(0xffffffffu, l0, 2);
    l1 += __shfl_xor_sync(0xffffffffu, l1, 1);
    l1 += __shfl_xor_sync(0xffffffffu, l1, 2);

    // ---- Epilogue: G = (T/l).Mhi + (T/l).Mlo  (2-pass, hi-only T) ----
    const float i0 = 1.f / l0, i1 = 1.f / l1;
    uint32_t thi[4][4];
#pragma unroll
    for (int ks = 0; ks < 4; ks++) {
        int t0 = 2 * ks, t1 = 2 * ks + 1;
        thi[ks][0] = pack_h2(O[t0][0] * i0, O[t0][1] * i0);
        thi[ks][1] = pack_h2(O[t0][2] * i1, O[t0][3] * i1);
        thi[ks][2] = pack_h2(O[t1][0] * i0, O[t1][1] * i0);
        thi[ks][3] = pack_h2(O[t1][2] * i1, O[t1][3] * i1);
    }

    CP_WAIT(0);
    __syncthreads();  // M_vd visible to all threads

    float gacc[8][4];
#pragma unroll
    for (int j = 0; j < 8; j++)
#pragma unroll
        for (int e = 0; e < 4; e++) gacc[j][e] = 0.f;

    {
        const uint32_t mh = smb + AT_MH;
        const uint32_t ml = smb + AT_ML;
#pragma unroll
        for (int jj = 0; jj < 4; jj++) {
#pragma unroll
            for (int ks = 0; ks < 4; ks++) {
                uint32_t off = (uint32_t)((16 * ks + v_row) * ROWB + 32 * jj + v_col);
                uint32_t bh0, bh1, bh2, bh3, bl0, bl1, bl2, bl3;
                LDSM_X4_T(bh0, bh1, bh2, bh3, mh + off);
                LDSM_X4_T(bl0, bl1, bl2, bl3, ml + off);
                mma16816(gacc[2 * jj],     thi[ks], bh0, bh1);
                mma16816(gacc[2 * jj],     thi[ks], bl0, bl1);
                mma16816(gacc[2 * jj + 1], thi[ks], bh2, bh3);
                mma16816(gacc[2 * jj + 1], thi[ks], bl2, bl3);
            }
        }
    }

    float* Gg = g_gate[br] + ((size_t)b * Nn + qt * 128) * 64;
#pragma unroll
    for (int j = 0; j < 8; j++) {
        int col = 8 * j + 2 * q4;
        *(float2*)(Gg + (size_t)r0 * 64 + col)       = make_float2(gacc[j][0], gacc[j][1]);
        *(float2*)(Gg + (size_t)(r0 + 8) * 64 + col) = make_float2(gacc[j][2], gacc[j][3]);
    }
}

// ---------------------------------------------------------------------------
// Kernel 3: elementwise gate. out = x * sigmoid(gt + gs + bdt + bds).
// ---------------------------------------------------------------------------
__global__ __launch_bounds__(256) void gate_kernel(
    const float* __restrict__ x,
    const float* __restrict__ bdt, const float* __restrict__ bds,
    float* __restrict__ out)
{
    __shared__ float bias[64];
    if (threadIdx.x < 64) bias[threadIdx.x] = bdt[threadIdx.x] + bds[threadIdx.x];
    __syncthreads();

    const size_t i = ((size_t)blockIdx.x * 256 + threadIdx.x) * 4;
    const int c = (int)(i & 63);

    float4 xv = *(const float4*)(x + i);
    float4 g0 = *(const float4*)(g_gate[0] + i);
    float4 g1 = *(const float4*)(g_gate[1] + i);
    float4 ov;
    ov.x = xv.x / (1.f + __expf(-(g0.x + g1.x + bias[c + 0])));
    ov.y = xv.y / (1.f + __expf(-(g0.y + g1.y + bias[c + 1])));
    ov.z = xv.z / (1.f + __expf(-(g0.z + g1.z + bias[c + 2])));
    ov.w = xv.w / (1.f + __expf(-(g0.w + g1.w + bias[c + 3])));
    *(float4*)(out + i) = ov;
}

// ---------------------------------------------------------------------------
extern "C" void kernel_launch(void* const* d_in, const int* in_sizes, int n_in,
                              void* d_out, int out_size)
{
    const float* x   = (const float*)d_in[0];
    const float* Wqt = (const float*)d_in[1];
    const float* Wkt = (const float*)d_in[2];
    const float* Wvt = (const float*)d_in[3];
    const float* Wqs = (const float*)d_in[4];
    const float* Wks = (const float*)d_in[5];
    const float* Wvs = (const float*)d_in[6];
    const float* Wdt = (const float*)d_in[7];
    const float* bdt = (const float*)d_in[8];
    const float* Wds = (const float*)d_in[9];
    const float* bds = (const float*)d_in[10];
    float* out = (float*)d_out;

    cudaFuncSetAttribute(attn_kernel, cudaFuncAttributeMaxDynamicSharedMemorySize, AT_SMEM);

    mm_w_kernel<<<4, 256>>>(Wqt, Wkt, Wqs, Wks, Wvt, Wdt, Wvs, Wds);

    xsplit_kernel<<<TOK * Dd / 1024, 256>>>(x);

    dim3 g2(4, Bb, 2);
    attn_kernel<<<g2, 256, AT_SMEM>>>(x);

    gate_kernel<<<TOK * Dd / 1024, 256>>>(x, bdt, bds, out);
}